// round 9
// baseline (speedup 1.0000x reference)
#include <cuda_runtime.h>
#include <cstdint>

#define BB 16
#define SS 2048
#define DD 256
#define LL 4
#define GD 1024
#define NF 6
#define NROW (BB*SS)

typedef unsigned long long u64;

// ---------------- static scratch (allocation-free) ----------------
__device__ float g_h[NROW * DD];          // residual stream
__device__ float g_gx[(size_t)NROW * GD]; // per-layer preactivations
__device__ float g_mu[NROW];
__device__ float g_rstd[NROW];
__device__ float g_Wp[DD * GD];           // gamma-folded Wx
__device__ float g_u[GD];
__device__ float g_v[GD];

// ---------------- f32x2 helpers ----------------
__device__ __forceinline__ void fma2(u64 &d, u64 a, u64 b) {
    asm("fma.rn.f32x2 %0,%1,%2,%0;" : "+l"(d) : "l"(a), "l"(b));
}
__device__ __forceinline__ u64 pk(float x, float y) {
    u64 r; asm("mov.b64 %0,{%1,%2};" : "=l"(r) : "f"(x), "f"(y)); return r;
}
__device__ __forceinline__ void upk(u64 v, float &x, float &y) {
    asm("mov.b64 {%0,%1},%2;" : "=f"(x), "=f"(y) : "l"(v));
}
__device__ __forceinline__ float tanh_ap(float x) {
    float r; asm("tanh.approx.f32 %0,%1;" : "=f"(r) : "f"(x)); return r;
}
__device__ __forceinline__ float rcp_ap(float x) {
    float r; asm("rcp.approx.f32 %0,%1;" : "=f"(r) : "f"(x)); return r;
}

// ---------------- cluster/DSMEM helpers ----------------
__device__ __forceinline__ unsigned smem_u32(const void* p) {
    unsigned r;
    asm("{ .reg .u64 t; cvta.to.shared.u64 t, %1; cvt.u32.u64 %0, t; }"
        : "=r"(r) : "l"(p));
    return r;
}
__device__ __forceinline__ unsigned mapa_u32(unsigned a, unsigned rank) {
    unsigned r; asm("mapa.shared::cluster.u32 %0, %1, %2;" : "=r"(r) : "r"(a), "r"(rank));
    return r;
}
// async remote scalar store: lands in remote smem, credits remote mbarrier tx.
__device__ __forceinline__ void st_async_remote(unsigned a, float v, unsigned rmbar) {
    asm volatile(
        "st.async.shared::cluster.mbarrier::complete_tx::bytes.f32 [%0], %1, [%2];"
        :: "r"(a), "f"(v), "r"(rmbar) : "memory");
}
__device__ __forceinline__ void mbar_init(unsigned a, unsigned cnt) {
    asm volatile("mbarrier.init.shared.b64 [%0], %1;" :: "r"(a), "r"(cnt) : "memory");
}
__device__ __forceinline__ void mbar_expect_tx(unsigned a, unsigned bytes) {
    asm volatile("mbarrier.arrive.expect_tx.shared.b64 _, [%0], %1;"
                 :: "r"(a), "r"(bytes) : "memory");
}
__device__ __forceinline__ void wait_parity(unsigned a, unsigned p) {
    asm volatile(
        "{\n\t.reg .pred P;\n"
        "LW%=:\n\t"
        "mbarrier.try_wait.parity.acquire.cluster.shared::cta.b64 P, [%0], %1, 0x989680;\n\t"
        "@P bra LD%=;\n\t"
        "bra LW%=;\n"
        "LD%=:\n\t}"
        :: "r"(a), "r"(p) : "memory");
}
__device__ __forceinline__ void cluster_sync_() {
    asm volatile("barrier.cluster.arrive.aligned;" ::: "memory");
    asm volatile("barrier.cluster.wait.aligned;" ::: "memory");
}

// ---------------- kernels ----------------
__global__ void k_inproj(const float* __restrict__ x, const float* __restrict__ tf,
                         const float* __restrict__ inW, const float* __restrict__ inb) {
    int row = blockIdx.x, d = threadIdx.x;
    float acc = inb[d] + __ldg(x + row) * inW[d];
#pragma unroll
    for (int f = 0; f < NF; f++)
        acc += __ldg(tf + (size_t)row * NF + f) * inW[(1 + f) * DD + d];
    g_h[(size_t)row * DD + d] = acc;
}

__global__ void k_stats() {
    int row = blockIdx.x * 8 + (threadIdx.x >> 5);
    int lane = threadIdx.x & 31;
    const float* p = g_h + (size_t)row * DD;
    float s = 0.f, s2 = 0.f;
#pragma unroll
    for (int i = lane; i < DD; i += 32) { float v = p[i]; s += v; s2 += v * v; }
#pragma unroll
    for (int o = 16; o > 0; o >>= 1) {
        s  += __shfl_xor_sync(0xffffffffu, s, o);
        s2 += __shfl_xor_sync(0xffffffffu, s2, o);
    }
    if (lane == 0) {
        float mu = s * (1.f / DD);
        float var = s2 * (1.f / DD) - mu * mu;
        g_mu[row] = mu;
        g_rstd[row] = rsqrtf(var + 1e-5f);
    }
}

__global__ void k_fold(const float* __restrict__ Wx, const float* __restrict__ lng,
                       const float* __restrict__ lnb, const float* __restrict__ bg, int l) {
    int j = blockIdx.x * 256 + threadIdx.x;
    const float* W = Wx + (size_t)l * DD * GD;
    float u = 0.f, v = 0.f;
    for (int k = 0; k < DD; k++) {
        float w  = W[(size_t)k * GD + j];
        float gk = lng[l * DD + k];
        g_Wp[(size_t)k * GD + j] = w * gk;
        u += gk * w;
        v += lnb[l * DD + k] * w;
    }
    g_u[j] = u;
    g_v[j] = v + bg[(size_t)l * GD + j];
}

#define PA 260
#define PB 258
#define GEMM_SMEM ((64 * PA + 128 * PB) * 4)   // 198,656 bytes

__global__ void __launch_bounds__(256) k_gemm() {
    extern __shared__ float sm[];
    float* As = sm;               // [64][PA]  (row, k)
    float* Bs = sm + 64 * PA;     // [128][PB] (col, k)
    int m0 = blockIdx.x * 64;
    int n0 = blockIdx.y * 128;

    for (int idx = threadIdx.x; idx < 64 * 64; idx += 256) {
        int r = idx >> 6, k4 = (idx & 63) << 2;
        float4 vv = *(const float4*)(g_h + (size_t)(m0 + r) * DD + k4);
        *(float4*)(As + r * PA + k4) = vv;
    }
    for (int idx = threadIdx.x; idx < 128 * DD; idx += 256) {
        int k = idx >> 7, c = idx & 127;
        Bs[c * PB + k] = g_Wp[(size_t)k * GD + n0 + c];
    }
    __syncthreads();

    int tc = threadIdx.x & 15;
    int tr = threadIdx.x >> 4;
    int r0 = tr * 4;

    u64 acc[4][8];
#pragma unroll
    for (int r = 0; r < 4; r++)
#pragma unroll
        for (int j = 0; j < 8; j++) acc[r][j] = 0ull;

#pragma unroll 4
    for (int k = 0; k < DD; k += 2) {
        u64 a2[4], b2[8];
#pragma unroll
        for (int r = 0; r < 4; r++) a2[r] = *(const u64*)(As + (r0 + r) * PA + k);
#pragma unroll
        for (int j = 0; j < 8; j++) b2[j] = *(const u64*)(Bs + (tc + 16 * j) * PB + k);
#pragma unroll
        for (int r = 0; r < 4; r++)
#pragma unroll
            for (int j = 0; j < 8; j++) fma2(acc[r][j], a2[r], b2[j]);
    }

#pragma unroll
    for (int r = 0; r < 4; r++) {
        int row = m0 + r0 + r;
        float rs = g_rstd[row];
        float rm = rs * g_mu[row];
#pragma unroll
        for (int j = 0; j < 8; j++) {
            int colg = n0 + tc + 16 * j;
            float xe, yo; upk(acc[r][j], xe, yo);
            g_gx[(size_t)row * GD + colg] = rs * (xe + yo) - rm * g_u[colg] + g_v[colg];
        }
    }
}

// ---- sLSTM recurrence: 8-CTA cluster/batch, scalar st.async, prefetch rings -
#define TX_BYTES (8 * 32 * 4)   // 1024 B of h per step per consumer barrier

__global__ void __launch_bounds__(256, 1) __cluster_dims__(8, 1, 1)
k_rec(const float* __restrict__ Wh, int l) {
    int c = blockIdx.x;               // cluster rank 0..7, owns dims [c*32, c*32+32)
    int b = blockIdx.y;               // batch
    int tid = threadIdx.x;
    int col = tid >> 1;               // gate-column 0..127 (g*32+dl)
    int khalf = tid & 1;              // K split: adjacent lanes share a column
    int g = col >> 5, dl = col & 31;
    int gcol = g * DD + c * 32 + dl;  // global gate-column
    int k0 = khalf * 128;

    __shared__ __align__(16) float hbuf[2][DD];   // pushed h (double-buffered)
    __shared__ float gbuf[128];
    __shared__ __align__(8) unsigned long long mbar[2];

    // weights: Wh[k0..k0+127, gcol] packed as 64 f32x2 in registers
    const float* W = Wh + (size_t)l * DD * GD;
    u64 wq[64];
#pragma unroll
    for (int i = 0; i < 64; i++) {
        float w0 = __ldg(W + (size_t)(k0 + 2 * i)     * GD + gcol);
        float w1 = __ldg(W + (size_t)(k0 + 2 * i + 1) * GD + gcol);
        wq[i] = pk(w0, w1);
    }

    unsigned mb0 = smem_u32(&mbar[0]), mb1 = smem_u32(&mbar[1]);
    if (tid == 0) {
        mbar_init(mb0, 1);
        mbar_init(mb1, 1);
        mbar_expect_tx(mb0, TX_BYTES);   // arm for step-0 stores
        mbar_expect_tx(mb1, TX_BYTES);   // arm for step-1 stores
    }
    __syncthreads();
    cluster_sync_();   // barriers live before any remote st.async

    // parity-0 remote addresses; parity-1 = +1024 (hbuf) / +8 (mbar)
    unsigned raddr0[8], rmb0[8];
    if (tid < 32) {
        unsigned la = smem_u32(&hbuf[0][c * 32 + tid]);
#pragma unroll
        for (int r = 0; r < 8; r++) {
            raddr0[r] = mapa_u32(la, r);
            rmb0[r]   = mapa_u32(mb0, r);
        }
    }

    const float* gxp = g_gx + (size_t)b * SS * GD;
    float* hres = g_h + (size_t)b * SS * DD;

    float st_c = 0.f, st_n = 0.f, st_m = 0.f;

    // depth-4 prefetch shift-rings for gx and residual h
    float gxA, gxB, gxC, gxD;
    float hrA = 0.f, hrB = 0.f, hrC = 0.f, hrD = 0.f;
    gxA = __ldg(gxp + 0 * GD + gcol);
    gxB = __ldg(gxp + 1 * GD + gcol);
    gxC = __ldg(gxp + 2 * GD + gcol);
    gxD = __ldg(gxp + 3 * GD + gcol);
    if (tid < 32) {
        hrA = __ldg(hres + 0 * DD + c * 32 + tid);
        hrB = __ldg(hres + 1 * DD + c * 32 + tid);
        hrC = __ldg(hres + 2 * DD + c * 32 + tid);
        hrD = __ldg(hres + 3 * DD + c * 32 + tid);
    }

    for (int s = 0; s < SS; s++) {
        float gxv = gxA, hrv = hrA;
        gxA = gxB; gxB = gxC; gxC = gxD;
        hrA = hrB; hrB = hrC; hrC = hrD;
        if (s + 4 < SS) {
            gxD = __ldg(gxp + (size_t)(s + 4) * GD + gcol);   // lands ~4 steps out
            if (tid < 32) hrD = __ldg(hres + (size_t)(s + 4) * DD + c * 32 + tid);
        }

        float dotv = 0.f;
        if (s > 0) {
            int pb = (s - 1) & 1;
            unsigned mb = pb ? mb1 : mb0;
            wait_parity(mb, ((s - 1) >> 1) & 1);
            if (tid == 0) mbar_expect_tx(mb, TX_BYTES);  // re-arm for step s+1
            const ulonglong2* h4 = (const ulonglong2*)(&hbuf[pb][k0]);
            u64 a0 = 0ull, a1 = 0ull, a2 = 0ull, a3 = 0ull;
#pragma unroll
            for (int i = 0; i < 16; i++) {
                ulonglong2 hv = h4[i];
                fma2(a0, hv.x, wq[2 * i]);
                fma2(a1, hv.y, wq[2 * i + 1]);
            }
#pragma unroll
            for (int i = 16; i < 32; i++) {
                ulonglong2 hv = h4[i];
                fma2(a2, hv.x, wq[2 * i]);
                fma2(a3, hv.y, wq[2 * i + 1]);
            }
            float x0, y0, x1, y1, x2, y2, x3, y3;
            upk(a0, x0, y0); upk(a1, x1, y1);
            upk(a2, x2, y2); upk(a3, x3, y3);
            dotv = ((x0 + y0) + (x1 + y1)) + ((x2 + y2) + (x3 + y3));
        }
        float full = dotv + __shfl_xor_sync(0xffffffffu, dotv, 1);
        if (!khalf) gbuf[col] = gxv + full;
        __syncthreads();

        if (tid < 32) {
            float it = gbuf[tid];
            float ft = gbuf[32 + tid];
            float zt = gbuf[64 + tid];
            float ot = gbuf[96 + tid];
            float mn = fmaxf(ft + st_m, it);
            float ip  = __expf(it - mn);
            float fp2 = __expf(ft + st_m - mn);
            st_c = fp2 * st_c + ip * tanh_ap(zt);
            st_n = fp2 * st_n + ip;
            st_m = mn;
            float sig = rcp_ap(1.f + __expf(-ot));
            float hv = sig * st_c * rcp_ap(fmaxf(fabsf(st_n), 1.f));
            hres[(size_t)s * DD + c * 32 + tid] = hrv + hv;
            if (s < SS - 1) {
                unsigned doff = (s & 1) ? 1024u : 0u;
                unsigned moff = (s & 1) ? 8u : 0u;
#pragma unroll
                for (int r = 0; r < 8; r++)
                    st_async_remote(raddr0[r] + doff, hv, rmb0[r] + moff);
            }
        }
    }
    cluster_sync_();   // don't exit with inbound remote stores in flight
}

__global__ void k_out(const float* __restrict__ fcW, const float* __restrict__ fcb,
                      float* __restrict__ out) {
    int b = blockIdx.x, t = threadIdx.x;
    __shared__ float red[256];
    red[t] = g_h[((size_t)b * SS + SS - 1) * DD + t] * fcW[t];
    __syncthreads();
    for (int o = 128; o > 0; o >>= 1) {
        if (t < o) red[t] += red[t + o];
        __syncthreads();
    }
    if (t == 0) out[b] = red[0] + fcb[0];
}

// ---------------- host ----------------
extern "C" void kernel_launch(void* const* d_in, const int* in_sizes, int n_in,
                              void* d_out, int out_size) {
    const float* x    = (const float*)d_in[0];
    const float* tf   = (const float*)d_in[1];
    const float* inW  = (const float*)d_in[2];
    const float* inb  = (const float*)d_in[3];
    const float* lng  = (const float*)d_in[4];
    const float* lnb  = (const float*)d_in[5];
    const float* Wx   = (const float*)d_in[6];
    const float* Wh   = (const float*)d_in[7];
    const float* bg   = (const float*)d_in[8];
    const float* fcW  = (const float*)d_in[9];
    const float* fcb  = (const float*)d_in[10];
    float* out = (float*)d_out;

    cudaFuncSetAttribute(k_gemm, cudaFuncAttributeMaxDynamicSharedMemorySize, GEMM_SMEM);

    k_inproj<<<NROW, 256>>>(x, tf, inW, inb);
    for (int l = 0; l < LL; l++) {
        k_stats<<<NROW / 8, 256>>>();
        k_fold<<<4, 256>>>(Wx, lng, lnb, bg, l);
        k_gemm<<<dim3(NROW / 64, GD / 128), 256, GEMM_SMEM>>>();
        k_rec<<<dim3(8, BB), 256>>>(Wh, l);
    }
    k_out<<<BB, 256>>>(fcW, fcb, out);
}

// round 12
// speedup vs baseline: 1.6390x; 1.6390x over previous
#include <cuda_runtime.h>
#include <cstdint>

#define BB 16
#define SS 2048
#define DD 256
#define LL 4
#define GD 1024
#define NF 6
#define NROW (BB*SS)

typedef unsigned long long u64;

// ---------------- static scratch (allocation-free) ----------------
__device__ float g_h[NROW * DD];          // residual stream
__device__ float g_gx[(size_t)NROW * GD]; // per-layer preactivations
__device__ float g_mu[NROW];
__device__ float g_rstd[NROW];
__device__ float g_Wp[DD * GD];           // gamma-folded Wx
__device__ float g_u[GD];
__device__ float g_v[GD];

// ---------------- f32x2 helpers ----------------
__device__ __forceinline__ void fma2(u64 &d, u64 a, u64 b) {
    asm("fma.rn.f32x2 %0,%1,%2,%0;" : "+l"(d) : "l"(a), "l"(b));
}
__device__ __forceinline__ u64 pk(float x, float y) {
    u64 r; asm("mov.b64 %0,{%1,%2};" : "=l"(r) : "f"(x), "f"(y)); return r;
}
__device__ __forceinline__ void upk(u64 v, float &x, float &y) {
    asm("mov.b64 {%0,%1},%2;" : "=f"(x), "=f"(y) : "l"(v));
}
__device__ __forceinline__ float tanh_ap(float x) {
    float r; asm("tanh.approx.f32 %0,%1;" : "=f"(r) : "f"(x)); return r;
}
__device__ __forceinline__ float rcp_ap(float x) {
    float r; asm("rcp.approx.f32 %0,%1;" : "=f"(r) : "f"(x)); return r;
}

// ---------------- cluster/DSMEM helpers ----------------
__device__ __forceinline__ unsigned smem_u32(const void* p) {
    unsigned r;
    asm("{ .reg .u64 t; cvta.to.shared.u64 t, %1; cvt.u32.u64 %0, t; }"
        : "=r"(r) : "l"(p));
    return r;
}
__device__ __forceinline__ unsigned mapa_u32(unsigned a, unsigned rank) {
    unsigned r; asm("mapa.shared::cluster.u32 %0, %1, %2;" : "=r"(r) : "r"(a), "r"(rank));
    return r;
}
// async remote 8-byte store: lands in remote smem, credits remote mbarrier tx.
__device__ __forceinline__ void st_async_remote64(unsigned a, u64 v, unsigned rmbar) {
    asm volatile(
        "st.async.shared::cluster.mbarrier::complete_tx::bytes.b64 [%0], %1, [%2];"
        :: "r"(a), "l"(v), "r"(rmbar) : "memory");
}
__device__ __forceinline__ void mbar_init(unsigned a, unsigned cnt) {
    asm volatile("mbarrier.init.shared.b64 [%0], %1;" :: "r"(a), "r"(cnt) : "memory");
}
__device__ __forceinline__ void mbar_expect_tx(unsigned a, unsigned bytes) {
    asm volatile("mbarrier.arrive.expect_tx.shared.b64 _, [%0], %1;"
                 :: "r"(a), "r"(bytes) : "memory");
}
__device__ __forceinline__ void wait_parity(unsigned a, unsigned p) {
    asm volatile(
        "{\n\t.reg .pred P;\n"
        "LW%=:\n\t"
        "mbarrier.try_wait.parity.acquire.cluster.shared::cta.b64 P, [%0], %1, 0x989680;\n\t"
        "@P bra LD%=;\n\t"
        "bra LW%=;\n"
        "LD%=:\n\t}"
        :: "r"(a), "r"(p) : "memory");
}
__device__ __forceinline__ void cluster_sync_() {
    asm volatile("barrier.cluster.arrive.aligned;" ::: "memory");
    asm volatile("barrier.cluster.wait.aligned;" ::: "memory");
}

// ---------------- kernels ----------------
__global__ void k_inproj(const float* __restrict__ x, const float* __restrict__ tf,
                         const float* __restrict__ inW, const float* __restrict__ inb) {
    int row = blockIdx.x, d = threadIdx.x;
    float acc = inb[d] + __ldg(x + row) * inW[d];
#pragma unroll
    for (int f = 0; f < NF; f++)
        acc += __ldg(tf + (size_t)row * NF + f) * inW[(1 + f) * DD + d];
    g_h[(size_t)row * DD + d] = acc;
}

__global__ void k_stats() {
    int row = blockIdx.x * 8 + (threadIdx.x >> 5);
    int lane = threadIdx.x & 31;
    const float* p = g_h + (size_t)row * DD;
    float s = 0.f, s2 = 0.f;
#pragma unroll
    for (int i = lane; i < DD; i += 32) { float v = p[i]; s += v; s2 += v * v; }
#pragma unroll
    for (int o = 16; o > 0; o >>= 1) {
        s  += __shfl_xor_sync(0xffffffffu, s, o);
        s2 += __shfl_xor_sync(0xffffffffu, s2, o);
    }
    if (lane == 0) {
        float mu = s * (1.f / DD);
        float var = s2 * (1.f / DD) - mu * mu;
        g_mu[row] = mu;
        g_rstd[row] = rsqrtf(var + 1e-5f);
    }
}

__global__ void k_fold(const float* __restrict__ Wx, const float* __restrict__ lng,
                       const float* __restrict__ lnb, const float* __restrict__ bg, int l) {
    int j = blockIdx.x * 256 + threadIdx.x;
    const float* W = Wx + (size_t)l * DD * GD;
    float u = 0.f, v = 0.f;
    for (int k = 0; k < DD; k++) {
        float w  = W[(size_t)k * GD + j];
        float gk = lng[l * DD + k];
        g_Wp[(size_t)k * GD + j] = w * gk;
        u += gk * w;
        v += lnb[l * DD + k] * w;
    }
    g_u[j] = u;
    g_v[j] = v + bg[(size_t)l * GD + j];
}

// GEMM: 64x128 tile, K in two 128-chunks -> 100.3 KB smem -> 2 CTAs/SM.
#define PAG 132
#define PBG 130
#define GEMM_SMEM ((64 * PAG + 128 * PBG) * 4)   // 100,352 bytes

__global__ void __launch_bounds__(256, 2) k_gemm() {
    extern __shared__ float sm[];
    float* As = sm;               // [64][PAG]  (row, kk)
    float* Bs = sm + 64 * PAG;    // [128][PBG] (col, kk)
    int m0 = blockIdx.x * 64;
    int n0 = blockIdx.y * 128;

    int tc = threadIdx.x & 15;
    int tr = threadIdx.x >> 4;
    int r0 = tr * 4;

    u64 acc[4][8];
#pragma unroll
    for (int r = 0; r < 4; r++)
#pragma unroll
        for (int j = 0; j < 8; j++) acc[r][j] = 0ull;

#pragma unroll
    for (int kc = 0; kc < DD; kc += 128) {
        __syncthreads();   // previous chunk's reads done before overwrite
        for (int idx = threadIdx.x; idx < 64 * 32; idx += 256) {   // A chunk
            int r = idx >> 5, k4 = (idx & 31) << 2;
            float4 vv = *(const float4*)(g_h + (size_t)(m0 + r) * DD + kc + k4);
            *(float4*)(As + r * PAG + k4) = vv;
        }
        for (int idx = threadIdx.x; idx < 128 * 128; idx += 256) { // B chunk transpose
            int kk = idx >> 7, c = idx & 127;
            Bs[c * PBG + kk] = g_Wp[(size_t)(kc + kk) * GD + n0 + c];
        }
        __syncthreads();

#pragma unroll 4
        for (int k = 0; k < 128; k += 2) {
            u64 a2[4], b2[8];
#pragma unroll
            for (int r = 0; r < 4; r++) a2[r] = *(const u64*)(As + (r0 + r) * PAG + k);
#pragma unroll
            for (int j = 0; j < 8; j++) b2[j] = *(const u64*)(Bs + (tc + 16 * j) * PBG + k);
#pragma unroll
            for (int r = 0; r < 4; r++)
#pragma unroll
                for (int j = 0; j < 8; j++) fma2(acc[r][j], a2[r], b2[j]);
        }
    }

#pragma unroll
    for (int r = 0; r < 4; r++) {
        int row = m0 + r0 + r;
        float rs = g_rstd[row];
        float rm = rs * g_mu[row];
#pragma unroll
        for (int j = 0; j < 8; j++) {
            int colg = n0 + tc + 16 * j;
            float xe, yo; upk(acc[r][j], xe, yo);
            g_gx[(size_t)row * GD + colg] = rs * (xe + yo) - rm * g_u[colg] + g_v[colg];
        }
    }
}

// ---- sLSTM recurrence: 8-CTA cluster per batch, b64 st.async exchange ------
#define TX_BYTES (8 * 32 * 4)   // 1024 B of h per step per consumer barrier

__global__ void __launch_bounds__(256, 1) __cluster_dims__(8, 1, 1)
k_rec(const float* __restrict__ Wh, int l) {
    int c = blockIdx.x;               // cluster rank 0..7, owns dims [c*32, c*32+32)
    int b = blockIdx.y;               // batch
    int tid = threadIdx.x;
    int col = tid >> 1;               // gate-column 0..127 (g*32+dl)
    int khalf = tid & 1;              // K split: adjacent lanes share a column
    int g = col >> 5, dl = col & 31;
    int gcol = g * DD + c * 32 + dl;  // global gate-column
    int k0 = khalf * 128;

    __shared__ __align__(16) float hbuf[2][DD];   // pushed h (double-buffered)
    __shared__ float gbuf[128];
    __shared__ __align__(8) unsigned long long mbar[2];

    // weights: Wh[k0..k0+127, gcol] packed as 64 f32x2 in registers
    const float* W = Wh + (size_t)l * DD * GD;
    u64 wq[64];
#pragma unroll
    for (int i = 0; i < 64; i++) {
        float w0 = __ldg(W + (size_t)(k0 + 2 * i)     * GD + gcol);
        float w1 = __ldg(W + (size_t)(k0 + 2 * i + 1) * GD + gcol);
        wq[i] = pk(w0, w1);
    }

    unsigned mb0 = smem_u32(&mbar[0]), mb1 = smem_u32(&mbar[1]);
    if (tid == 0) {
        mbar_init(mb0, 1);
        mbar_init(mb1, 1);
        mbar_expect_tx(mb0, TX_BYTES);   // arm for step-0 stores
        mbar_expect_tx(mb1, TX_BYTES);   // arm for step-1 stores
    }
    __syncthreads();
    cluster_sync_();   // barriers live before any remote st.async

    // remote data + barrier addresses (even producer lanes push b64 pairs)
    unsigned raddr[2][8], rmb[2][8];
    if (tid < 32) {
        int d = c * 32 + tid;
#pragma unroll
        for (int p = 0; p < 2; p++) {
            unsigned la = smem_u32(&hbuf[p][d]);
            unsigned lm = (p == 0) ? mb0 : mb1;
#pragma unroll
            for (int r = 0; r < 8; r++) {
                raddr[p][r] = mapa_u32(la, r);
                rmb[p][r]   = mapa_u32(lm, r);
            }
        }
    }

    const float* gxp = g_gx + (size_t)b * SS * GD;
    float* hres = g_h + (size_t)b * SS * DD;

    float st_c = 0.f, st_n = 0.f, st_m = 0.f;

    for (int s = 0; s < SS; s++) {
        float gxv = __ldg(gxp + (size_t)s * GD + gcol);
        float hrv = 0.f;
        if (tid < 32) hrv = hres[(size_t)s * DD + c * 32 + tid];

        float dotv = 0.f;
        if (s > 0) {
            int pb = (s - 1) & 1;
            unsigned mb = pb ? mb1 : mb0;
            wait_parity(mb, ((s - 1) >> 1) & 1);
            if (tid == 0) mbar_expect_tx(mb, TX_BYTES);  // re-arm for step s+1
            const ulonglong2* h4 = (const ulonglong2*)(&hbuf[pb][k0]);
            u64 a0 = 0ull, a1 = 0ull;
#pragma unroll
            for (int i = 0; i < 32; i++) {
                ulonglong2 hv = h4[i];
                fma2(a0, hv.x, wq[2 * i]);
                fma2(a1, hv.y, wq[2 * i + 1]);
            }
            float l0, h0, l1, h1;
            upk(a0, l0, h0); upk(a1, l1, h1);
            dotv = (l0 + h0) + (l1 + h1);
        }
        float full = dotv + __shfl_xor_sync(0xffffffffu, dotv, 1);
        if (!khalf) gbuf[col] = gxv + full;
        __syncthreads();

        if (tid < 32) {
            float it = gbuf[tid];
            float ft = gbuf[32 + tid];
            float zt = gbuf[64 + tid];
            float ot = gbuf[96 + tid];
            float mn = fmaxf(ft + st_m, it);
            float ip  = __expf(it - mn);
            float fp2 = __expf(ft + st_m - mn);
            st_c = fp2 * st_c + ip * tanh_ap(zt);
            st_n = fp2 * st_n + ip;
            st_m = mn;
            float sig = rcp_ap(1.f + __expf(-ot));
            float hv = sig * st_c * rcp_ap(fmaxf(fabsf(st_n), 1.f));
            hres[(size_t)s * DD + c * 32 + tid] = hrv + hv;
            // pack (h[2i], h[2i+1]) on even lanes; send b64 to all 8 ranks
            float hov = __shfl_down_sync(0xffffffffu, hv, 1);
            if (s < SS - 1 && !(tid & 1)) {
                u64 pv = pk(hv, hov);
                int p = s & 1;
#pragma unroll
                for (int r = 0; r < 8; r++)
                    st_async_remote64(raddr[p][r], pv, rmb[p][r]);
            }
        }
    }
    cluster_sync_();   // don't exit with inbound remote stores in flight
}

__global__ void k_out(const float* __restrict__ fcW, const float* __restrict__ fcb,
                      float* __restrict__ out) {
    int b = blockIdx.x, t = threadIdx.x;
    __shared__ float red[256];
    red[t] = g_h[((size_t)b * SS + SS - 1) * DD + t] * fcW[t];
    __syncthreads();
    for (int o = 128; o > 0; o >>= 1) {
        if (t < o) red[t] += red[t + o];
        __syncthreads();
    }
    if (t == 0) out[b] = red[0] + fcb[0];
}

// ---------------- host ----------------
extern "C" void kernel_launch(void* const* d_in, const int* in_sizes, int n_in,
                              void* d_out, int out_size) {
    const float* x    = (const float*)d_in[0];
    const float* tf   = (const float*)d_in[1];
    const float* inW  = (const float*)d_in[2];
    const float* inb  = (const float*)d_in[3];
    const float* lng  = (const float*)d_in[4];
    const float* lnb  = (const float*)d_in[5];
    const float* Wx   = (const float*)d_in[6];
    const float* Wh   = (const float*)d_in[7];
    const float* bg   = (const float*)d_in[8];
    const float* fcW  = (const float*)d_in[9];
    const float* fcb  = (const float*)d_in[10];
    float* out = (float*)d_out;

    cudaFuncSetAttribute(k_gemm, cudaFuncAttributeMaxDynamicSharedMemorySize, GEMM_SMEM);

    k_inproj<<<NROW, 256>>>(x, tf, inW, inb);
    for (int l = 0; l < LL; l++) {
        k_stats<<<NROW / 8, 256>>>();
        k_fold<<<4, 256>>>(Wx, lng, lnb, bg, l);
        k_gemm<<<dim3(NROW / 64, GD / 128), 256, GEMM_SMEM>>>();
        k_rec<<<dim3(8, BB), 256>>>(Wh, l);
    }
    k_out<<<BB, 256>>>(fcW, fcb, out);
}